// round 2
// baseline (speedup 1.0000x reference)
#include <cuda_runtime.h>
#include <cuda_bf16.h>
#include <math.h>

#define SEQ   2048
#define HID   2048
#define NH    16
#define DK    64
#define DV    128
#define KEYD  1024
#define VALD  2048
#define CDIM  4096   // 2*KEYD + VALD

// ------------------------------------------------------------------
// Scratch (device globals; no allocation allowed)
// ------------------------------------------------------------------
__device__ float g_mixed[SEQ * CDIM];   // pre-conv qkv
__device__ float g_qkv  [SEQ * CDIM];   // post conv+silu (q | k | v)
__device__ float g_g    [SEQ * NH];     // log-decay
__device__ float g_beta [SEQ * NH];
__device__ float g_z    [SEQ * VALD];
__device__ float g_core [SEQ * VALD];
__device__ float g_gated[SEQ * VALD];

// ------------------------------------------------------------------
// Generic fp32 NT GEMM:  C[M,N] = A[M,K] * B[N,K]^T   (all row-major)
// BM=BN=128, BK=8, 256 threads, 8x8 per-thread tile.
// M,N multiples of 128; K multiple of 8. No bounds checks.
// ------------------------------------------------------------------
__global__ __launch_bounds__(256)
void sgemm_nt(const float* __restrict__ A, const float* __restrict__ B,
              float* __restrict__ C, int M, int N, int K)
{
    __shared__ float As[8][128];
    __shared__ float Bs[8][128];

    const int tid  = threadIdx.x;
    const int bx   = blockIdx.x;   // N tile
    const int by   = blockIdx.y;   // M tile

    const int lrow = tid >> 1;            // 0..127
    const int lk   = (tid & 1) * 4;       // 0 or 4
    const float* Ap = A + (size_t)(by * 128 + lrow) * K + lk;
    const float* Bp = B + (size_t)(bx * 128 + lrow) * K + lk;

    const int tx = tid & 15;   // 0..15 -> 8 cols each
    const int ty = tid >> 4;   // 0..15 -> 8 rows each

    float acc[8][8];
#pragma unroll
    for (int i = 0; i < 8; i++)
#pragma unroll
        for (int j = 0; j < 8; j++) acc[i][j] = 0.f;

    for (int k0 = 0; k0 < K; k0 += 8) {
        float4 av = *(const float4*)(Ap + k0);
        float4 bv = *(const float4*)(Bp + k0);
        __syncthreads();
        As[lk + 0][lrow] = av.x; As[lk + 1][lrow] = av.y;
        As[lk + 2][lrow] = av.z; As[lk + 3][lrow] = av.w;
        Bs[lk + 0][lrow] = bv.x; Bs[lk + 1][lrow] = bv.y;
        Bs[lk + 2][lrow] = bv.z; Bs[lk + 3][lrow] = bv.w;
        __syncthreads();

#pragma unroll
        for (int kk = 0; kk < 8; kk++) {
            float a[8], b[8];
            float4 a0 = *(const float4*)&As[kk][ty * 8];
            float4 a1 = *(const float4*)&As[kk][ty * 8 + 4];
            float4 b0 = *(const float4*)&Bs[kk][tx * 8];
            float4 b1 = *(const float4*)&Bs[kk][tx * 8 + 4];
            a[0]=a0.x;a[1]=a0.y;a[2]=a0.z;a[3]=a0.w;a[4]=a1.x;a[5]=a1.y;a[6]=a1.z;a[7]=a1.w;
            b[0]=b0.x;b[1]=b0.y;b[2]=b0.z;b[3]=b0.w;b[4]=b1.x;b[5]=b1.y;b[6]=b1.z;b[7]=b1.w;
#pragma unroll
            for (int i = 0; i < 8; i++)
#pragma unroll
                for (int j = 0; j < 8; j++)
                    acc[i][j] = fmaf(a[i], b[j], acc[i][j]);
        }
    }

#pragma unroll
    for (int i = 0; i < 8; i++) {
        float* Cp = C + (size_t)(by * 128 + ty * 8 + i) * N + bx * 128 + tx * 8;
        float4 c0 = make_float4(acc[i][0], acc[i][1], acc[i][2], acc[i][3]);
        float4 c1 = make_float4(acc[i][4], acc[i][5], acc[i][6], acc[i][7]);
        *(float4*)(Cp)     = c0;
        *(float4*)(Cp + 4) = c1;
    }
}

// ------------------------------------------------------------------
// Depthwise causal conv (K=4) along time + SiLU.
// mixed layout (t, c) row-major; conv_w layout (c, 1, 4).
// ------------------------------------------------------------------
__global__ __launch_bounds__(256)
void conv_silu_kernel(const float* __restrict__ mixed,
                      const float* __restrict__ w,
                      float* __restrict__ out)
{
    int idx = blockIdx.x * blockDim.x + threadIdx.x;   // t*CDIM + c
    int t = idx >> 12;
    int c = idx & (CDIM - 1);
    float w0 = w[c * 4 + 0], w1 = w[c * 4 + 1], w2 = w[c * 4 + 2], w3 = w[c * 4 + 3];
    float acc = w3 * mixed[idx];
    if (t >= 1) acc = fmaf(w2, mixed[idx - CDIM],     acc);
    if (t >= 2) acc = fmaf(w1, mixed[idx - 2 * CDIM], acc);
    if (t >= 3) acc = fmaf(w0, mixed[idx - 3 * CDIM], acc);
    out[idx] = acc / (1.f + expf(-acc));   // silu
}

// ------------------------------------------------------------------
// a/b projections -> g (log decay) and beta. One warp per (t,h).
// ------------------------------------------------------------------
__global__ __launch_bounds__(256)
void ab_kernel(const float* __restrict__ hs,
               const float* __restrict__ Wa,
               const float* __restrict__ Wb,
               const float* __restrict__ A_log,
               const float* __restrict__ dt_bias,
               float* __restrict__ g,
               float* __restrict__ beta)
{
    int w    = blockIdx.x * (blockDim.x >> 5) + (threadIdx.x >> 5);
    int lane = threadIdx.x & 31;
    if (w >= SEQ * NH) return;
    int t = w >> 4, h = w & 15;

    const float4* x4 = (const float4*)(hs + (size_t)t * HID);
    const float4* a4 = (const float4*)(Wa + (size_t)h * HID);
    const float4* b4 = (const float4*)(Wb + (size_t)h * HID);

    float sa = 0.f, sb = 0.f;
    for (int i = lane; i < HID / 4; i += 32) {
        float4 x = x4[i], a = a4[i], b = b4[i];
        sa += x.x * a.x + x.y * a.y + x.z * a.z + x.w * a.w;
        sb += x.x * b.x + x.y * b.y + x.z * b.z + x.w * b.w;
    }
#pragma unroll
    for (int o = 16; o; o >>= 1) {
        sa += __shfl_xor_sync(0xffffffffu, sa, o);
        sb += __shfl_xor_sync(0xffffffffu, sb, o);
    }
    if (lane == 0) {
        float av = sa + dt_bias[h];
        float sp = (av > 20.f) ? av : log1pf(expf(av));   // softplus
        g[t * NH + h]    = -expf(A_log[h]) * sp;
        beta[t * NH + h] = 1.f / (1.f + expf(-sb));
    }
}

// ------------------------------------------------------------------
// L2-normalize q (and scale 1/sqrt(DK)) and k, per (t,h). Warp per row.
// ------------------------------------------------------------------
__global__ __launch_bounds__(256)
void l2norm_kernel(float* __restrict__ qkv)
{
    int w    = blockIdx.x * (blockDim.x >> 5) + (threadIdx.x >> 5);
    int lane = threadIdx.x & 31;
    if (w >= SEQ * NH) return;
    int t = w >> 4, h = w & 15;

    float2* qp = (float2*)(qkv + (size_t)t * CDIM + h * DK);
    float2* kp = (float2*)(qkv + (size_t)t * CDIM + KEYD + h * DK);
    float2 qv = qp[lane];
    float2 kv = kp[lane];
    float sq = qv.x * qv.x + qv.y * qv.y;
    float sk = kv.x * kv.x + kv.y * kv.y;
#pragma unroll
    for (int o = 16; o; o >>= 1) {
        sq += __shfl_xor_sync(0xffffffffu, sq, o);
        sk += __shfl_xor_sync(0xffffffffu, sk, o);
    }
    float rq = rsqrtf(sq + 1e-6f) * 0.125f;   // * 1/sqrt(64)
    float rk = rsqrtf(sk + 1e-6f);
    qp[lane] = make_float2(qv.x * rq, qv.y * rq);
    kp[lane] = make_float2(kv.x * rk, kv.y * rk);
}

// ------------------------------------------------------------------
// Delta-rule scan. Grid = 16 blocks (one head), 128 threads (one per v).
// Each thread keeps a 64-float state column in registers.
// qkv row layout: [ q (KEYD) | k (KEYD) | v (VALD) ]
// ------------------------------------------------------------------
__global__ __launch_bounds__(128)
void scan_kernel(const float* __restrict__ qkv,
                 const float* __restrict__ g,
                 const float* __restrict__ beta,
                 float* __restrict__ core)
{
    const int h = blockIdx.x;
    const int v = threadIdx.x;

    __shared__ float sk[DK];
    __shared__ float sq[DK];

    float S[DK];
#pragma unroll
    for (int i = 0; i < DK; i++) S[i] = 0.f;

    for (int t = 0; t < SEQ; t++) {
        const float* row = qkv + (size_t)t * CDIM;
        float vt = row[2 * KEYD + h * DV + v];
        float gt = g[t * NH + h];
        float bt = beta[t * NH + h];

        __syncthreads();
        if (v < 16)
            ((float4*)sk)[v] = ((const float4*)(row + KEYD + h * DK))[v];      // k
        else if (v < 32)
            ((float4*)sq)[v - 16] = ((const float4*)(row + h * DK))[v - 16];   // q
        __syncthreads();

        float eg = expf(gt);
        float raw = 0.f;
        const float4* sk4 = (const float4*)sk;
        const float4* sq4 = (const float4*)sq;
#pragma unroll
        for (int i = 0; i < 16; i++) {
            float4 kf = sk4[i];
            raw = fmaf(kf.x, S[4 * i + 0], raw);
            raw = fmaf(kf.y, S[4 * i + 1], raw);
            raw = fmaf(kf.z, S[4 * i + 2], raw);
            raw = fmaf(kf.w, S[4 * i + 3], raw);
        }
        float delta = (vt - eg * raw) * bt;

        float o = 0.f;
#pragma unroll
        for (int i = 0; i < 16; i++) {
            float4 kf = sk4[i];
            float4 qf = sq4[i];
            float s0 = fmaf(S[4 * i + 0], eg, kf.x * delta);
            float s1 = fmaf(S[4 * i + 1], eg, kf.y * delta);
            float s2 = fmaf(S[4 * i + 2], eg, kf.z * delta);
            float s3 = fmaf(S[4 * i + 3], eg, kf.w * delta);
            S[4 * i + 0] = s0; S[4 * i + 1] = s1;
            S[4 * i + 2] = s2; S[4 * i + 3] = s3;
            o = fmaf(qf.x, s0, o);
            o = fmaf(qf.y, s1, o);
            o = fmaf(qf.z, s2, o);
            o = fmaf(qf.w, s3, o);
        }
        core[(size_t)t * VALD + h * DV + v] = o;
    }
}

// ------------------------------------------------------------------
// Gated RMSNorm over DV=128 + SiLU(z) gate. Warp per (t,h).
// ------------------------------------------------------------------
__global__ __launch_bounds__(256)
void gate_norm_kernel(const float* __restrict__ core,
                      const float* __restrict__ z,
                      const float* __restrict__ norm_w,
                      float* __restrict__ out)
{
    int w    = blockIdx.x * (blockDim.x >> 5) + (threadIdx.x >> 5);
    int lane = threadIdx.x & 31;
    if (w >= SEQ * NH) return;
    int t = w >> 4, h = w & 15;
    size_t base = (size_t)t * VALD + h * DV;

    float4 cv = ((const float4*)(core + base))[lane];
    float ss = cv.x * cv.x + cv.y * cv.y + cv.z * cv.z + cv.w * cv.w;
#pragma unroll
    for (int o = 16; o; o >>= 1) ss += __shfl_xor_sync(0xffffffffu, ss, o);
    float r = rsqrtf(ss * (1.f / DV) + 1e-6f);

    float4 zv = ((const float4*)(z + base))[lane];
    float4 nw = ((const float4*)norm_w)[lane];
    float4 ov;
    ov.x = cv.x * r * nw.x * (zv.x / (1.f + expf(-zv.x)));
    ov.y = cv.y * r * nw.y * (zv.y / (1.f + expf(-zv.y)));
    ov.z = cv.z * r * nw.z * (zv.z / (1.f + expf(-zv.z)));
    ov.w = cv.w * r * nw.w * (zv.w / (1.f + expf(-zv.w)));
    ((float4*)(out + base))[lane] = ov;
}

// ------------------------------------------------------------------
// Launch
// ------------------------------------------------------------------
extern "C" void kernel_launch(void* const* d_in, const int* in_sizes, int n_in,
                              void* d_out, int out_size)
{
    const float* hs      = (const float*)d_in[0];
    const float* Wqkv    = (const float*)d_in[1];
    const float* Wa      = (const float*)d_in[2];
    const float* Wb      = (const float*)d_in[3];
    const float* Wz      = (const float*)d_in[4];
    const float* convw   = (const float*)d_in[5];
    const float* A_log   = (const float*)d_in[6];
    const float* dt_bias = (const float*)d_in[7];
    const float* norm_w  = (const float*)d_in[8];
    const float* Wout    = (const float*)d_in[9];
    float* out = (float*)d_out;

    float *p_mixed, *p_qkv, *p_g, *p_beta, *p_z, *p_core, *p_gated;
    cudaGetSymbolAddress((void**)&p_mixed, g_mixed);
    cudaGetSymbolAddress((void**)&p_qkv,   g_qkv);
    cudaGetSymbolAddress((void**)&p_g,     g_g);
    cudaGetSymbolAddress((void**)&p_beta,  g_beta);
    cudaGetSymbolAddress((void**)&p_z,     g_z);
    cudaGetSymbolAddress((void**)&p_core,  g_core);
    cudaGetSymbolAddress((void**)&p_gated, g_gated);

    // 1) mixed = hs @ Wqkv^T  (2048 x 4096)
    sgemm_nt<<<dim3(CDIM / 128, SEQ / 128), 256>>>(hs, Wqkv, p_mixed, SEQ, CDIM, HID);

    // 2) depthwise causal conv + silu
    conv_silu_kernel<<<(SEQ * CDIM) / 256, 256>>>(p_mixed, convw, p_qkv);

    // 3) g / beta
    ab_kernel<<<(SEQ * NH) / 8, 256>>>(hs, Wa, Wb, A_log, dt_bias, p_g, p_beta);

    // 4) z = hs @ Wz^T (2048 x 2048)
    sgemm_nt<<<dim3(VALD / 128, SEQ / 128), 256>>>(hs, Wz, p_z, SEQ, VALD, HID);

    // 5) l2 normalize q,k
    l2norm_kernel<<<(SEQ * NH) / 8, 256>>>(p_qkv);

    // 6) sequential delta-rule scan
    scan_kernel<<<NH, 128>>>(p_qkv, p_g, p_beta, p_core);

    // 7) gated rmsnorm + silu(z)
    gate_norm_kernel<<<(SEQ * NH) / 8, 256>>>(p_core, p_z, norm_w, p_gated);

    // 8) out = gated @ Wout^T  (2048 x 2048)
    sgemm_nt<<<dim3(HID / 128, SEQ / 128), 256>>>(p_gated, Wout, out, SEQ, HID, VALD);
}

// round 3
// speedup vs baseline: 1.5918x; 1.5918x over previous
#include <cuda_runtime.h>
#include <cuda_bf16.h>
#include <math.h>

#define SEQ   2048
#define HID   2048
#define NH    16
#define DK    64
#define DV    128
#define KEYD  1024
#define VALD  2048
#define CDIM  4096   // 2*KEYD + VALD

// ------------------------------------------------------------------
// Scratch (device globals; no allocation allowed)
// ------------------------------------------------------------------
__device__ float g_mixed[SEQ * CDIM];   // pre-conv qkv
__device__ float g_qkv  [SEQ * CDIM];   // post conv+silu (q | k | v)
__device__ float g_eg   [SEQ * NH];     // exp(log-decay)
__device__ float g_beta [SEQ * NH];
__device__ float g_z    [SEQ * VALD];
__device__ float g_core [SEQ * VALD];
__device__ float g_gated[SEQ * VALD];

// ------------------------------------------------------------------
// fp32 NT GEMM: C[M,N] = A[M,K] * B[N,K]^T  (row-major)
// BM=BN=128, BK=16, 256 threads, 8x8 microtile, double-buffered smem.
// M,N multiples of 128; K multiple of 16.
// ------------------------------------------------------------------
__global__ __launch_bounds__(256)
void sgemm_nt(const float* __restrict__ A, const float* __restrict__ B,
              float* __restrict__ C, int M, int N, int K)
{
    __shared__ float As[2][16][128];
    __shared__ float Bs[2][16][128];

    const int tid = threadIdx.x;
    const int bx  = blockIdx.x;    // N tile
    const int by  = blockIdx.y;    // M tile

    const int lrow = tid >> 1;          // 0..127
    const int lk   = (tid & 1) * 8;     // 0 or 8
    const float* Ap = A + (size_t)(by * 128 + lrow) * K + lk;
    const float* Bp = B + (size_t)(bx * 128 + lrow) * K + lk;

    const int tx = tid & 15;    // 0..15
    const int ty = tid >> 4;    // 0..15

    float acc[8][8];
#pragma unroll
    for (int i = 0; i < 8; i++)
#pragma unroll
        for (int j = 0; j < 8; j++) acc[i][j] = 0.f;

    float4 a0 = *(const float4*)(Ap);
    float4 a1 = *(const float4*)(Ap + 4);
    float4 b0 = *(const float4*)(Bp);
    float4 b1 = *(const float4*)(Bp + 4);

#define STORE_AB(buf)                                              \
    do {                                                           \
        As[buf][lk + 0][lrow] = a0.x; As[buf][lk + 1][lrow] = a0.y;\
        As[buf][lk + 2][lrow] = a0.z; As[buf][lk + 3][lrow] = a0.w;\
        As[buf][lk + 4][lrow] = a1.x; As[buf][lk + 5][lrow] = a1.y;\
        As[buf][lk + 6][lrow] = a1.z; As[buf][lk + 7][lrow] = a1.w;\
        Bs[buf][lk + 0][lrow] = b0.x; Bs[buf][lk + 1][lrow] = b0.y;\
        Bs[buf][lk + 2][lrow] = b0.z; Bs[buf][lk + 3][lrow] = b0.w;\
        Bs[buf][lk + 4][lrow] = b1.x; Bs[buf][lk + 5][lrow] = b1.y;\
        Bs[buf][lk + 6][lrow] = b1.z; Bs[buf][lk + 7][lrow] = b1.w;\
    } while (0)

#define COMPUTE(buf)                                                       \
    do {                                                                   \
        _Pragma("unroll")                                                  \
        for (int kk = 0; kk < 16; kk++) {                                  \
            float4 fa0 = *(const float4*)&As[buf][kk][ty * 8];             \
            float4 fa1 = *(const float4*)&As[buf][kk][ty * 8 + 4];         \
            float4 fb0 = *(const float4*)&Bs[buf][kk][tx * 4];             \
            float4 fb1 = *(const float4*)&Bs[buf][kk][64 + tx * 4];        \
            float av[8] = {fa0.x, fa0.y, fa0.z, fa0.w,                     \
                           fa1.x, fa1.y, fa1.z, fa1.w};                    \
            float bv[8] = {fb0.x, fb0.y, fb0.z, fb0.w,                     \
                           fb1.x, fb1.y, fb1.z, fb1.w};                    \
            _Pragma("unroll")                                              \
            for (int i = 0; i < 8; i++)                                    \
                _Pragma("unroll")                                          \
                for (int j = 0; j < 8; j++)                                \
                    acc[i][j] = fmaf(av[i], bv[j], acc[i][j]);             \
        }                                                                  \
    } while (0)

    STORE_AB(0);
    __syncthreads();

    int buf = 0;
    for (int k0 = 16; k0 < K; k0 += 16) {
        a0 = *(const float4*)(Ap + k0);
        a1 = *(const float4*)(Ap + k0 + 4);
        b0 = *(const float4*)(Bp + k0);
        b1 = *(const float4*)(Bp + k0 + 4);
        COMPUTE(buf);
        STORE_AB(buf ^ 1);
        __syncthreads();
        buf ^= 1;
    }
    COMPUTE(buf);

#pragma unroll
    for (int i = 0; i < 8; i++) {
        float* Cp = C + (size_t)(by * 128 + ty * 8 + i) * N + bx * 128 + tx * 4;
        *(float4*)(Cp)      = make_float4(acc[i][0], acc[i][1], acc[i][2], acc[i][3]);
        *(float4*)(Cp + 64) = make_float4(acc[i][4], acc[i][5], acc[i][6], acc[i][7]);
    }
#undef STORE_AB
#undef COMPUTE
}

// ------------------------------------------------------------------
// Depthwise causal conv (K=4) along time + SiLU.
// ------------------------------------------------------------------
__global__ __launch_bounds__(256)
void conv_silu_kernel(const float* __restrict__ mixed,
                      const float* __restrict__ w,
                      float* __restrict__ out)
{
    int idx = blockIdx.x * blockDim.x + threadIdx.x;   // t*CDIM + c
    int t = idx >> 12;
    int c = idx & (CDIM - 1);
    float w0 = w[c * 4 + 0], w1 = w[c * 4 + 1], w2 = w[c * 4 + 2], w3 = w[c * 4 + 3];
    float acc = w3 * mixed[idx];
    if (t >= 1) acc = fmaf(w2, mixed[idx - CDIM],     acc);
    if (t >= 2) acc = fmaf(w1, mixed[idx - 2 * CDIM], acc);
    if (t >= 3) acc = fmaf(w0, mixed[idx - 3 * CDIM], acc);
    out[idx] = acc / (1.f + expf(-acc));   // silu
}

// ------------------------------------------------------------------
// a/b projections -> eg = exp(log-decay) and beta. One warp per (t,h).
// ------------------------------------------------------------------
__global__ __launch_bounds__(256)
void ab_kernel(const float* __restrict__ hs,
               const float* __restrict__ Wa,
               const float* __restrict__ Wb,
               const float* __restrict__ A_log,
               const float* __restrict__ dt_bias,
               float* __restrict__ eg,
               float* __restrict__ beta)
{
    int w    = blockIdx.x * (blockDim.x >> 5) + (threadIdx.x >> 5);
    int lane = threadIdx.x & 31;
    if (w >= SEQ * NH) return;
    int t = w >> 4, h = w & 15;

    const float4* x4 = (const float4*)(hs + (size_t)t * HID);
    const float4* a4 = (const float4*)(Wa + (size_t)h * HID);
    const float4* b4 = (const float4*)(Wb + (size_t)h * HID);

    float sa = 0.f, sb = 0.f;
    for (int i = lane; i < HID / 4; i += 32) {
        float4 x = x4[i], a = a4[i], b = b4[i];
        sa += x.x * a.x + x.y * a.y + x.z * a.z + x.w * a.w;
        sb += x.x * b.x + x.y * b.y + x.z * b.z + x.w * b.w;
    }
#pragma unroll
    for (int o = 16; o; o >>= 1) {
        sa += __shfl_xor_sync(0xffffffffu, sa, o);
        sb += __shfl_xor_sync(0xffffffffu, sb, o);
    }
    if (lane == 0) {
        float av = sa + dt_bias[h];
        float sp = (av > 20.f) ? av : log1pf(expf(av));   // softplus
        eg[t * NH + h]   = expf(-expf(A_log[h]) * sp);
        beta[t * NH + h] = 1.f / (1.f + expf(-sb));
    }
}

// ------------------------------------------------------------------
// L2-normalize q (scale 1/sqrt(DK)) and k, per (t,h). Warp per row.
// ------------------------------------------------------------------
__global__ __launch_bounds__(256)
void l2norm_kernel(float* __restrict__ qkv)
{
    int w    = blockIdx.x * (blockDim.x >> 5) + (threadIdx.x >> 5);
    int lane = threadIdx.x & 31;
    if (w >= SEQ * NH) return;
    int t = w >> 4, h = w & 15;

    float2* qp = (float2*)(qkv + (size_t)t * CDIM + h * DK);
    float2* kp = (float2*)(qkv + (size_t)t * CDIM + KEYD + h * DK);
    float2 qv = qp[lane];
    float2 kv = kp[lane];
    float sq = qv.x * qv.x + qv.y * qv.y;
    float sk = kv.x * kv.x + kv.y * kv.y;
#pragma unroll
    for (int o = 16; o; o >>= 1) {
        sq += __shfl_xor_sync(0xffffffffu, sq, o);
        sk += __shfl_xor_sync(0xffffffffu, sk, o);
    }
    float rq = rsqrtf(sq + 1e-6f) * 0.125f;   // * 1/sqrt(64)
    float rk = rsqrtf(sk + 1e-6f);
    qp[lane] = make_float2(qv.x * rq, qv.y * rq);
    kp[lane] = make_float2(kv.x * rk, kv.y * rk);
}

// ------------------------------------------------------------------
// Delta-rule scan, DK split 4 ways.
// Grid = 64 blocks: block = (head h = bid>>2, v-group vg = bid&3).
// 128 threads: quarter = tid&3 (16 of DK each), vl = tid>>2 (32 v's).
// Per-thread state: 16 floats. Shuffle-reduce over the 4 quarters.
// qkv row layout: [ q (KEYD) | k (KEYD) | v (VALD) ]
// ------------------------------------------------------------------
__global__ __launch_bounds__(128)
void scan_kernel(const float* __restrict__ qkv,
                 const float* __restrict__ eg_arr,
                 const float* __restrict__ beta,
                 float* __restrict__ core)
{
    const int h   = blockIdx.x >> 2;
    const int vg  = blockIdx.x & 3;
    const int tid = threadIdx.x;
    const int qtr = tid & 3;
    const int vl  = tid >> 2;
    const int v   = vg * 32 + vl;

    __shared__ float kq[2][128];   // [0:64] = k, [64:128] = q

    float S[16];
#pragma unroll
    for (int i = 0; i < 16; i++) S[i] = 0.f;

    // preload t = 0
    kq[0][tid] = (tid < 64) ? qkv[KEYD + h * DK + tid]
                            : qkv[h * DK + (tid - 64)];
    float vt = qkv[2 * KEYD + h * DV + v];
    float eg = eg_arr[h];
    float bt = beta[h];
    __syncthreads();

    for (int t = 0; t < SEQ; t++) {
        const int cur = t & 1;

        // prefetch t+1 (global -> regs), hidden under compute
        float kqn = 0.f, vtn = 0.f, egn = 0.f, btn = 0.f;
        if (t + 1 < SEQ) {
            const float* rn = qkv + (size_t)(t + 1) * CDIM;
            kqn = (tid < 64) ? rn[KEYD + h * DK + tid]
                             : rn[h * DK + (tid - 64)];
            vtn = rn[2 * KEYD + h * DV + v];
            egn = eg_arr[(t + 1) * NH + h];
            btn = beta[(t + 1) * NH + h];
        }

        const float4* k4 = (const float4*)&kq[cur][qtr * 16];
        const float4* q4 = (const float4*)&kq[cur][64 + qtr * 16];
        float4 kf[4], qf[4];
#pragma unroll
        for (int i = 0; i < 4; i++) { kf[i] = k4[i]; qf[i] = q4[i]; }

        // raw = k . S (partial over this quarter, 4 chains)
        float r0 = 0.f, r1 = 0.f, r2 = 0.f, r3 = 0.f;
#pragma unroll
        for (int i = 0; i < 4; i++) {
            r0 = fmaf(kf[i].x, S[4 * i + 0], r0);
            r1 = fmaf(kf[i].y, S[4 * i + 1], r1);
            r2 = fmaf(kf[i].z, S[4 * i + 2], r2);
            r3 = fmaf(kf[i].w, S[4 * i + 3], r3);
        }
        float raw = (r0 + r1) + (r2 + r3);
        raw += __shfl_xor_sync(0xffffffffu, raw, 1);
        raw += __shfl_xor_sync(0xffffffffu, raw, 2);

        float delta = (vt - eg * raw) * bt;

        // S = eg*S + k*delta ; o partial = q . S
        float o0 = 0.f, o1 = 0.f, o2 = 0.f, o3 = 0.f;
#pragma unroll
        for (int i = 0; i < 4; i++) {
            float s0 = fmaf(S[4 * i + 0], eg, kf[i].x * delta);
            float s1 = fmaf(S[4 * i + 1], eg, kf[i].y * delta);
            float s2 = fmaf(S[4 * i + 2], eg, kf[i].z * delta);
            float s3 = fmaf(S[4 * i + 3], eg, kf[i].w * delta);
            S[4 * i + 0] = s0; S[4 * i + 1] = s1;
            S[4 * i + 2] = s2; S[4 * i + 3] = s3;
            o0 = fmaf(qf[i].x, s0, o0);
            o1 = fmaf(qf[i].y, s1, o1);
            o2 = fmaf(qf[i].z, s2, o2);
            o3 = fmaf(qf[i].w, s3, o3);
        }
        float o = (o0 + o1) + (o2 + o3);
        o += __shfl_xor_sync(0xffffffffu, o, 1);
        o += __shfl_xor_sync(0xffffffffu, o, 2);
        if (qtr == 0)
            core[(size_t)t * VALD + h * DV + v] = o;

        // stage t+1 into the other buffer (safe: last reads of it synced)
        if (t + 1 < SEQ)
            kq[cur ^ 1][tid] = kqn;
        vt = vtn; eg = egn; bt = btn;
        __syncthreads();
    }
}

// ------------------------------------------------------------------
// Gated RMSNorm over DV=128 + SiLU(z) gate. Warp per (t,h).
// ------------------------------------------------------------------
__global__ __launch_bounds__(256)
void gate_norm_kernel(const float* __restrict__ core,
                      const float* __restrict__ z,
                      const float* __restrict__ norm_w,
                      float* __restrict__ out)
{
    int w    = blockIdx.x * (blockDim.x >> 5) + (threadIdx.x >> 5);
    int lane = threadIdx.x & 31;
    if (w >= SEQ * NH) return;
    int t = w >> 4, h = w & 15;
    size_t base = (size_t)t * VALD + h * DV;

    float4 cv = ((const float4*)(core + base))[lane];
    float ss = cv.x * cv.x + cv.y * cv.y + cv.z * cv.z + cv.w * cv.w;
#pragma unroll
    for (int o = 16; o; o >>= 1) ss += __shfl_xor_sync(0xffffffffu, ss, o);
    float r = rsqrtf(ss * (1.f / DV) + 1e-6f);

    float4 zv = ((const float4*)(z + base))[lane];
    float4 nw = ((const float4*)norm_w)[lane];
    float4 ov;
    ov.x = cv.x * r * nw.x * (zv.x / (1.f + expf(-zv.x)));
    ov.y = cv.y * r * nw.y * (zv.y / (1.f + expf(-zv.y)));
    ov.z = cv.z * r * nw.z * (zv.z / (1.f + expf(-zv.z)));
    ov.w = cv.w * r * nw.w * (zv.w / (1.f + expf(-zv.w)));
    ((float4*)(out + base))[lane] = ov;
}

// ------------------------------------------------------------------
// Launch: fork ab + z GEMM onto a side stream; join before consumers.
// ------------------------------------------------------------------
static cudaStream_t g_sB = nullptr;
static cudaEvent_t  g_evFork = nullptr, g_evAB = nullptr, g_evZ = nullptr;

extern "C" void kernel_launch(void* const* d_in, const int* in_sizes, int n_in,
                              void* d_out, int out_size)
{
    const float* hs      = (const float*)d_in[0];
    const float* Wqkv    = (const float*)d_in[1];
    const float* Wa      = (const float*)d_in[2];
    const float* Wb      = (const float*)d_in[3];
    const float* Wz      = (const float*)d_in[4];
    const float* convw   = (const float*)d_in[5];
    const float* A_log   = (const float*)d_in[6];
    const float* dt_bias = (const float*)d_in[7];
    const float* norm_w  = (const float*)d_in[8];
    const float* Wout    = (const float*)d_in[9];
    float* out = (float*)d_out;

    if (!g_sB) {
        cudaStreamCreateWithFlags(&g_sB, cudaStreamNonBlocking);
        cudaEventCreateWithFlags(&g_evFork, cudaEventDisableTiming);
        cudaEventCreateWithFlags(&g_evAB,   cudaEventDisableTiming);
        cudaEventCreateWithFlags(&g_evZ,    cudaEventDisableTiming);
    }

    float *p_mixed, *p_qkv, *p_eg, *p_beta, *p_z, *p_core, *p_gated;
    cudaGetSymbolAddress((void**)&p_mixed, g_mixed);
    cudaGetSymbolAddress((void**)&p_qkv,   g_qkv);
    cudaGetSymbolAddress((void**)&p_eg,    g_eg);
    cudaGetSymbolAddress((void**)&p_beta,  g_beta);
    cudaGetSymbolAddress((void**)&p_z,     g_z);
    cudaGetSymbolAddress((void**)&p_core,  g_core);
    cudaGetSymbolAddress((void**)&p_gated, g_gated);

    // Fork side stream
    cudaEventRecord(g_evFork, 0);
    cudaStreamWaitEvent(g_sB, g_evFork, 0);

    // Side stream: eg/beta, then z GEMM (independent of main chain)
    ab_kernel<<<(SEQ * NH) / 8, 256, 0, g_sB>>>(hs, Wa, Wb, A_log, dt_bias, p_eg, p_beta);
    cudaEventRecord(g_evAB, g_sB);
    sgemm_nt<<<dim3(VALD / 128, SEQ / 128), 256, 0, g_sB>>>(hs, Wz, p_z, SEQ, VALD, HID);
    cudaEventRecord(g_evZ, g_sB);

    // Main stream
    sgemm_nt<<<dim3(CDIM / 128, SEQ / 128), 256>>>(hs, Wqkv, p_mixed, SEQ, CDIM, HID);
    conv_silu_kernel<<<(SEQ * CDIM) / 256, 256>>>(p_mixed, convw, p_qkv);
    l2norm_kernel<<<(SEQ * NH) / 8, 256>>>(p_qkv);

    cudaStreamWaitEvent(0, g_evAB, 0);
    scan_kernel<<<64, 128>>>(p_qkv, p_eg, p_beta, p_core);

    cudaStreamWaitEvent(0, g_evZ, 0);
    gate_norm_kernel<<<(SEQ * NH) / 8, 256>>>(p_core, p_z, norm_w, p_gated);
    sgemm_nt<<<dim3(HID / 128, SEQ / 128), 256>>>(p_gated, Wout, out, SEQ, HID, VALD);
}

// round 5
// speedup vs baseline: 3.2404x; 2.0357x over previous
#include <cuda_runtime.h>
#include <cuda_fp16.h>
#include <math.h>
#include <stdint.h>

#define SEQ   2048
#define HID   2048
#define NH    16
#define DK    64
#define DV    128
#define KEYD  1024
#define VALD  2048
#define CDIM  4096   // 2*KEYD + VALD

// ------------------------------------------------------------------
// Scratch (device globals; no allocation allowed)
// ------------------------------------------------------------------
__device__ float g_mixed[SEQ * CDIM];   // pre-conv qkv (fp32)
__device__ float g_qkv  [SEQ * CDIM];   // post conv+silu (q | k | v)
__device__ float g_eg   [SEQ * NH];     // exp(log-decay)
__device__ float g_beta [SEQ * NH];
__device__ float g_z    [SEQ * VALD];
__device__ float g_core [SEQ * VALD];

__device__ __half g_hs_h  [SEQ  * HID];
__device__ __half g_Wqkv_h[CDIM * HID];
__device__ __half g_Wz_h  [VALD * HID];
__device__ __half g_Wout_h[HID  * VALD];
__device__ __half g_gat_h [SEQ  * VALD];

// ------------------------------------------------------------------
// PTX helpers (base ISA only: cp.async / ldmatrix / mma.sync)
// ------------------------------------------------------------------
__device__ __forceinline__ uint32_t smem_u32(const void* p) {
    uint32_t a;
    asm("{ .reg .u64 t; cvta.to.shared.u64 t, %1; cvt.u32.u64 %0, t; }"
        : "=r"(a) : "l"(p));
    return a;
}
__device__ __forceinline__ void cp_async16(uint32_t s, const void* g) {
    asm volatile("cp.async.cg.shared.global [%0], [%1], 16;" :: "r"(s), "l"(g));
}
__device__ __forceinline__ void cp_commit() {
    asm volatile("cp.async.commit_group;");
}
template <int N>
__device__ __forceinline__ void cp_wait() {
    asm volatile("cp.async.wait_group %0;" :: "n"(N));
}
__device__ __forceinline__ void ldsm4(uint32_t& r0, uint32_t& r1,
                                      uint32_t& r2, uint32_t& r3, uint32_t a) {
    asm volatile("ldmatrix.sync.aligned.m8n8.x4.shared.b16 {%0,%1,%2,%3}, [%4];"
                 : "=r"(r0), "=r"(r1), "=r"(r2), "=r"(r3) : "r"(a));
}
__device__ __forceinline__ void mma16816(float* d, const uint32_t* a,
                                         uint32_t b0, uint32_t b1) {
    asm volatile(
        "mma.sync.aligned.m16n8k16.row.col.f32.f16.f16.f32 "
        "{%0,%1,%2,%3}, {%4,%5,%6,%7}, {%8,%9}, {%0,%1,%2,%3};"
        : "+f"(d[0]), "+f"(d[1]), "+f"(d[2]), "+f"(d[3])
        : "r"(a[0]), "r"(a[1]), "r"(a[2]), "r"(a[3]), "r"(b0), "r"(b1));
}
#define SW(off) ((off) ^ (((off) >> 3) & 0x70))

// ------------------------------------------------------------------
// fp16 NT GEMM via mma.sync: C[M,N] = A[M,K] * B[N,K]^T (fp32 out)
// BM=BN=128, BK=64, 256 threads (8 warps, 4x2), double-buffered cp.async.
// M,N mult of 128; K mult of 64. smem 64KB.
// ------------------------------------------------------------------
#define HGEMM_SMEM (4 * 16384)

__global__ __launch_bounds__(256)
void hgemm_nt(const __half* __restrict__ A, const __half* __restrict__ B,
              float* __restrict__ C, int M, int N, int K)
{
    extern __shared__ __align__(1024) char sm[];
    const int tid  = threadIdx.x;
    const int wid  = tid >> 5, lane = tid & 31;
    const int tileN = blockIdx.x, tileM = blockIdx.y;
    const int wm = (wid >> 1) * 32;     // warp M offset
    const int wn = (wid & 1) * 64;      // warp N offset

    const uint32_t sbase = smem_u32(sm);

    const char* Ag = (const char*)(A + (size_t)tileM * 128 * K);
    const char* Bg = (const char*)(B + (size_t)tileN * 128 * K);
    const size_t rs = (size_t)K * 2;

    // cp.async mapping: 256 threads cover 32 rows x 8 x 16B per pass; 4 passes.
    const int crow = tid >> 3;
    const int ccol = (tid & 7) * 16;
    const int csw  = SW(crow * 128 + ccol);   // smem offset (row-block invariant part varies; see below)

    // ldmatrix lane offsets (bytes within 128x128B tile), before k-step shift
    int offA[2], offB[4];
#pragma unroll
    for (int mt = 0; mt < 2; mt++)
        offA[mt] = (wm + mt * 16 + (lane & 15)) * 128 + (lane >> 4) * 16;
#pragma unroll
    for (int j2 = 0; j2 < 4; j2++)
        offB[j2] = (wn + j2 * 16 + (lane & 7) + ((lane >> 4) & 1) * 8) * 128
                 + ((lane >> 3) & 1) * 16;

    float acc[2][8][4];
#pragma unroll
    for (int mt = 0; mt < 2; mt++)
#pragma unroll
        for (int nt = 0; nt < 8; nt++)
#pragma unroll
            for (int r = 0; r < 4; r++) acc[mt][nt][r] = 0.f;

    const int chunks = K >> 6;

#define ISSUE(i, b)                                                          \
    do {                                                                     \
        uint32_t sA = sbase + (b) * 32768;                                   \
        uint32_t sB = sA + 16384;                                            \
        const char* gA = Ag + (size_t)(i) * 128 + ccol;                      \
        const char* gB = Bg + (size_t)(i) * 128 + ccol;                      \
        _Pragma("unroll")                                                    \
        for (int p = 0; p < 4; p++) {                                        \
            int row = crow + p * 32;                                         \
            int so  = SW(row * 128 + ccol);                                  \
            cp_async16(sA + so, gA + row * rs);                              \
            cp_async16(sB + so, gB + row * rs);                              \
        }                                                                    \
        cp_commit();                                                         \
    } while (0)

    ISSUE(0, 0);

    for (int i = 0; i < chunks; i++) {
        const int b = i & 1;
        if (i + 1 < chunks) { ISSUE(i + 1, b ^ 1); cp_wait<1>(); }
        else                { cp_wait<0>(); }
        __syncthreads();

        const uint32_t sA = sbase + b * 32768;
        const uint32_t sB = sA + 16384;
#pragma unroll
        for (int ks = 0; ks < 4; ks++) {
            uint32_t af[2][4];
#pragma unroll
            for (int mt = 0; mt < 2; mt++) {
                int off = offA[mt] + ks * 32;
                ldsm4(af[mt][0], af[mt][1], af[mt][2], af[mt][3], sA + SW(off));
            }
            uint32_t bf[8][2];
#pragma unroll
            for (int j2 = 0; j2 < 4; j2++) {
                int off = offB[j2] + ks * 32;
                uint32_t r0, r1, r2, r3;
                ldsm4(r0, r1, r2, r3, sB + SW(off));
                bf[2 * j2][0] = r0; bf[2 * j2][1] = r1;
                bf[2 * j2 + 1][0] = r2; bf[2 * j2 + 1][1] = r3;
            }
#pragma unroll
            for (int mt = 0; mt < 2; mt++)
#pragma unroll
                for (int nt = 0; nt < 8; nt++)
                    mma16816(acc[mt][nt], af[mt], bf[nt][0], bf[nt][1]);
        }
        __syncthreads();
    }
#undef ISSUE

    // epilogue
    const int gid = lane >> 2, ctg = lane & 3;
#pragma unroll
    for (int mt = 0; mt < 2; mt++) {
        int m0 = tileM * 128 + wm + mt * 16 + gid;
#pragma unroll
        for (int nt = 0; nt < 8; nt++) {
            int n0 = tileN * 128 + wn + nt * 8 + ctg * 2;
            *(float2*)(C + (size_t)m0 * N + n0) =
                make_float2(acc[mt][nt][0], acc[mt][nt][1]);
            *(float2*)(C + (size_t)(m0 + 8) * N + n0) =
                make_float2(acc[mt][nt][2], acc[mt][nt][3]);
        }
    }
}

// ------------------------------------------------------------------
// fp32 -> fp16 conversion, 8 elems/thread.
// ------------------------------------------------------------------
__global__ __launch_bounds__(256)
void f2h_kernel(const float* __restrict__ in, __half* __restrict__ out)
{
    int idx = (blockIdx.x * 256 + threadIdx.x) * 8;
    float4 x0 = *(const float4*)(in + idx);
    float4 x1 = *(const float4*)(in + idx + 4);
    union { __half2 h[4]; uint4 u; } r;
    r.h[0] = __floats2half2_rn(x0.x, x0.y);
    r.h[1] = __floats2half2_rn(x0.z, x0.w);
    r.h[2] = __floats2half2_rn(x1.x, x1.y);
    r.h[3] = __floats2half2_rn(x1.z, x1.w);
    *(uint4*)(out + idx) = r.u;
}

// ------------------------------------------------------------------
// Depthwise causal conv (K=4) along time + SiLU.
// ------------------------------------------------------------------
__global__ __launch_bounds__(256)
void conv_silu_kernel(const float* __restrict__ mixed,
                      const float* __restrict__ w,
                      float* __restrict__ out)
{
    int idx = blockIdx.x * blockDim.x + threadIdx.x;   // t*CDIM + c
    int t = idx >> 12;
    int c = idx & (CDIM - 1);
    float w0 = w[c * 4 + 0], w1 = w[c * 4 + 1], w2 = w[c * 4 + 2], w3 = w[c * 4 + 3];
    float acc = w3 * mixed[idx];
    if (t >= 1) acc = fmaf(w2, mixed[idx - CDIM],     acc);
    if (t >= 2) acc = fmaf(w1, mixed[idx - 2 * CDIM], acc);
    if (t >= 3) acc = fmaf(w0, mixed[idx - 3 * CDIM], acc);
    out[idx] = acc / (1.f + expf(-acc));   // silu
}

// ------------------------------------------------------------------
// a/b projections -> eg = exp(log-decay) and beta. One warp per (t,h).
// ------------------------------------------------------------------
__global__ __launch_bounds__(256)
void ab_kernel(const float* __restrict__ hs,
               const float* __restrict__ Wa,
               const float* __restrict__ Wb,
               const float* __restrict__ A_log,
               const float* __restrict__ dt_bias,
               float* __restrict__ eg,
               float* __restrict__ beta)
{
    int w    = blockIdx.x * (blockDim.x >> 5) + (threadIdx.x >> 5);
    int lane = threadIdx.x & 31;
    if (w >= SEQ * NH) return;
    int t = w >> 4, h = w & 15;

    const float4* x4 = (const float4*)(hs + (size_t)t * HID);
    const float4* a4 = (const float4*)(Wa + (size_t)h * HID);
    const float4* b4 = (const float4*)(Wb + (size_t)h * HID);

    float sa = 0.f, sb = 0.f;
    for (int i = lane; i < HID / 4; i += 32) {
        float4 x = x4[i], a = a4[i], b = b4[i];
        sa += x.x * a.x + x.y * a.y + x.z * a.z + x.w * a.w;
        sb += x.x * b.x + x.y * b.y + x.z * b.z + x.w * b.w;
    }
#pragma unroll
    for (int o = 16; o; o >>= 1) {
        sa += __shfl_xor_sync(0xffffffffu, sa, o);
        sb += __shfl_xor_sync(0xffffffffu, sb, o);
    }
    if (lane == 0) {
        float av = sa + dt_bias[h];
        float sp = (av > 20.f) ? av : log1pf(expf(av));   // softplus
        eg[t * NH + h]   = expf(-expf(A_log[h]) * sp);
        beta[t * NH + h] = 1.f / (1.f + expf(-sb));
    }
}

// ------------------------------------------------------------------
// L2-normalize q (scale 1/sqrt(DK)) and k, per (t,h). Warp per row.
// ------------------------------------------------------------------
__global__ __launch_bounds__(256)
void l2norm_kernel(float* __restrict__ qkv)
{
    int w    = blockIdx.x * (blockDim.x >> 5) + (threadIdx.x >> 5);
    int lane = threadIdx.x & 31;
    if (w >= SEQ * NH) return;
    int t = w >> 4, h = w & 15;

    float2* qp = (float2*)(qkv + (size_t)t * CDIM + h * DK);
    float2* kp = (float2*)(qkv + (size_t)t * CDIM + KEYD + h * DK);
    float2 qv = qp[lane];
    float2 kv = kp[lane];
    float sq = qv.x * qv.x + qv.y * qv.y;
    float sk = kv.x * kv.x + kv.y * kv.y;
#pragma unroll
    for (int o = 16; o; o >>= 1) {
        sq += __shfl_xor_sync(0xffffffffu, sq, o);
        sk += __shfl_xor_sync(0xffffffffu, sk, o);
    }
    float rq = rsqrtf(sq + 1e-6f) * 0.125f;   // * 1/sqrt(64)
    float rk = rsqrtf(sk + 1e-6f);
    qp[lane] = make_float2(qv.x * rq, qv.y * rq);
    kp[lane] = make_float2(kv.x * rk, kv.y * rk);
}

// ------------------------------------------------------------------
// Delta-rule scan, DK split 4 ways (unchanged from R3).
// ------------------------------------------------------------------
__global__ __launch_bounds__(128)
void scan_kernel(const float* __restrict__ qkv,
                 const float* __restrict__ eg_arr,
                 const float* __restrict__ beta,
                 float* __restrict__ core)
{
    const int h   = blockIdx.x >> 2;
    const int vg  = blockIdx.x & 3;
    const int tid = threadIdx.x;
    const int qtr = tid & 3;
    const int vl  = tid >> 2;
    const int v   = vg * 32 + vl;

    __shared__ float kq[2][128];   // [0:64] = k, [64:128] = q

    float S[16];
#pragma unroll
    for (int i = 0; i < 16; i++) S[i] = 0.f;

    kq[0][tid] = (tid < 64) ? qkv[KEYD + h * DK + tid]
                            : qkv[h * DK + (tid - 64)];
    float vt = qkv[2 * KEYD + h * DV + v];
    float eg = eg_arr[h];
    float bt = beta[h];
    __syncthreads();

    for (int t = 0; t < SEQ; t++) {
        const int cur = t & 1;

        float kqn = 0.f, vtn = 0.f, egn = 0.f, btn = 0.f;
        if (t + 1 < SEQ) {
            const float* rn = qkv + (size_t)(t + 1) * CDIM;
            kqn = (tid < 64) ? rn[KEYD + h * DK + tid]
                             : rn[h * DK + (tid - 64)];
            vtn = rn[2 * KEYD + h * DV + v];
            egn = eg_arr[(t + 1) * NH + h];
            btn = beta[(t + 1) * NH + h];
        }

        const float4* k4 = (const float4*)&kq[cur][qtr * 16];
        const float4* q4 = (const float4*)&kq[cur][64 + qtr * 16];
        float4 kf[4], qf[4];
#pragma unroll
        for (int i = 0; i < 4; i++) { kf[i] = k4[i]; qf[i] = q4[i]; }

        float r0 = 0.f, r1 = 0.f, r2 = 0.f, r3 = 0.f;
#pragma unroll
        for (int i = 0; i < 4; i++) {
            r0 = fmaf(kf[i].x, S[4 * i + 0], r0);
            r1 = fmaf(kf[i].y, S[4 * i + 1], r1);
            r2 = fmaf(kf[i].z, S[4 * i + 2], r2);
            r3 = fmaf(kf[i].w, S[4 * i + 3], r3);
        }
        float raw = (r0 + r1) + (r2 + r3);
        raw += __shfl_xor_sync(0xffffffffu, raw, 1);
        raw += __shfl_xor_sync(0xffffffffu, raw, 2);

        float delta = (vt - eg * raw) * bt;

        float o0 = 0.f, o1 = 0.f, o2 = 0.f, o3 = 0.f;
#pragma unroll
        for (int i = 0; i < 4; i++) {
            float s0 = fmaf(S[4 * i + 0], eg, kf[i].x * delta);
            float s1 = fmaf(S[4 * i + 1], eg, kf[i].y * delta);
            float s2 = fmaf(S[4 * i + 2], eg, kf[i].z * delta);
            float s3 = fmaf(S[4 * i + 3], eg, kf[i].w * delta);
            S[4 * i + 0] = s0; S[4 * i + 1] = s1;
            S[4 * i + 2] = s2; S[4 * i + 3] = s3;
            o0 = fmaf(qf[i].x, s0, o0);
            o1 = fmaf(qf[i].y, s1, o1);
            o2 = fmaf(qf[i].z, s2, o2);
            o3 = fmaf(qf[i].w, s3, o3);
        }
        float o = (o0 + o1) + (o2 + o3);
        o += __shfl_xor_sync(0xffffffffu, o, 1);
        o += __shfl_xor_sync(0xffffffffu, o, 2);
        if (qtr == 0)
            core[(size_t)t * VALD + h * DV + v] = o;

        if (t + 1 < SEQ)
            kq[cur ^ 1][tid] = kqn;
        vt = vtn; eg = egn; bt = btn;
        __syncthreads();
    }
}

// ------------------------------------------------------------------
// Gated RMSNorm + SiLU(z) gate, fp16 output. Warp per (t,h).
// ------------------------------------------------------------------
__global__ __launch_bounds__(256)
void gate_norm_h_kernel(const float* __restrict__ core,
                        const float* __restrict__ z,
                        const float* __restrict__ norm_w,
                        __half* __restrict__ out)
{
    int w    = blockIdx.x * (blockDim.x >> 5) + (threadIdx.x >> 5);
    int lane = threadIdx.x & 31;
    if (w >= SEQ * NH) return;
    int t = w >> 4, h = w & 15;
    size_t base = (size_t)t * VALD + h * DV;

    float4 cv = ((const float4*)(core + base))[lane];
    float ss = cv.x * cv.x + cv.y * cv.y + cv.z * cv.z + cv.w * cv.w;
#pragma unroll
    for (int o = 16; o; o >>= 1) ss += __shfl_xor_sync(0xffffffffu, ss, o);
    float r = rsqrtf(ss * (1.f / DV) + 1e-6f);

    float4 zv = ((const float4*)(z + base))[lane];
    float4 nw = ((const float4*)norm_w)[lane];
    float v0 = cv.x * r * nw.x * (zv.x / (1.f + expf(-zv.x)));
    float v1 = cv.y * r * nw.y * (zv.y / (1.f + expf(-zv.y)));
    float v2 = cv.z * r * nw.z * (zv.z / (1.f + expf(-zv.z)));
    float v3 = cv.w * r * nw.w * (zv.w / (1.f + expf(-zv.w)));

    union { __half2 h[2]; uint2 u; } o2;
    o2.h[0] = __floats2half2_rn(v0, v1);
    o2.h[1] = __floats2half2_rn(v2, v3);
    *(uint2*)(out + base + lane * 4 - lane * 4 + (size_t)0 + lane * 4) = o2.u;
}

// ------------------------------------------------------------------
// Launch
// ------------------------------------------------------------------
static cudaStream_t g_sB = nullptr;
static cudaEvent_t  g_evFork = nullptr, g_evHs = nullptr, g_evAB = nullptr,
                    g_evZ = nullptr, g_evWout = nullptr;

extern "C" void kernel_launch(void* const* d_in, const int* in_sizes, int n_in,
                              void* d_out, int out_size)
{
    const float* hs      = (const float*)d_in[0];
    const float* Wqkv    = (const float*)d_in[1];
    const float* Wa      = (const float*)d_in[2];
    const float* Wb      = (const float*)d_in[3];
    const float* Wz      = (const float*)d_in[4];
    const float* convw   = (const float*)d_in[5];
    const float* A_log   = (const float*)d_in[6];
    const float* dt_bias = (const float*)d_in[7];
    const float* norm_w  = (const float*)d_in[8];
    const float* Wout    = (const float*)d_in[9];
    float* out = (float*)d_out;

    if (!g_sB) {
        cudaStreamCreateWithFlags(&g_sB, cudaStreamNonBlocking);
        cudaEventCreateWithFlags(&g_evFork, cudaEventDisableTiming);
        cudaEventCreateWithFlags(&g_evHs,   cudaEventDisableTiming);
        cudaEventCreateWithFlags(&g_evAB,   cudaEventDisableTiming);
        cudaEventCreateWithFlags(&g_evZ,    cudaEventDisableTiming);
        cudaEventCreateWithFlags(&g_evWout, cudaEventDisableTiming);
        cudaFuncSetAttribute(hgemm_nt,
                             cudaFuncAttributeMaxDynamicSharedMemorySize, HGEMM_SMEM);
    }

    float *p_mixed, *p_qkv, *p_eg, *p_beta, *p_z, *p_core;
    __half *p_hs, *p_Wqkv, *p_Wz, *p_Wout, *p_gat;
    cudaGetSymbolAddress((void**)&p_mixed, g_mixed);
    cudaGetSymbolAddress((void**)&p_qkv,   g_qkv);
    cudaGetSymbolAddress((void**)&p_eg,    g_eg);
    cudaGetSymbolAddress((void**)&p_beta,  g_beta);
    cudaGetSymbolAddress((void**)&p_z,     g_z);
    cudaGetSymbolAddress((void**)&p_core,  g_core);
    cudaGetSymbolAddress((void**)&p_hs,    g_hs_h);
    cudaGetSymbolAddress((void**)&p_Wqkv,  g_Wqkv_h);
    cudaGetSymbolAddress((void**)&p_Wz,    g_Wz_h);
    cudaGetSymbolAddress((void**)&p_Wout,  g_Wout_h);
    cudaGetSymbolAddress((void**)&p_gat,   g_gat_h);

    // Fork side stream
    cudaEventRecord(g_evFork, 0);
    cudaStreamWaitEvent(g_sB, g_evFork, 0);

    // Main: hs -> fp16 (A operand for qkv and z GEMMs)
    f2h_kernel<<<(SEQ * HID / 8) / 256, 256>>>(hs, p_hs);
    cudaEventRecord(g_evHs, 0);

    // Side: eg/beta; Wz->fp16; z GEMM; Wout->fp16
    ab_kernel<<<(SEQ * NH) / 8, 256, 0, g_sB>>>(hs, Wa, Wb, A_log, dt_bias, p_eg, p_beta);
    cudaEventRecord(g_evAB, g_sB);
    f2h_kernel<<<(VALD * HID / 8) / 256, 256, 0, g_sB>>>(Wz, p_Wz);
    cudaStreamWaitEvent(g_sB, g_evHs, 0);
    hgemm_nt<<<dim3(VALD / 128, SEQ / 128), 256, HGEMM_SMEM, g_sB>>>(
        p_hs, p_Wz, p_z, SEQ, VALD, HID);
    cudaEventRecord(g_evZ, g_sB);
    f2h_kernel<<<(HID * VALD / 8) / 256, 256, 0, g_sB>>>(Wout, p_Wout);
    cudaEventRecord(g_evWout, g_sB);

    // Main: qkv GEMM chain
    f2h_kernel<<<(CDIM * HID / 8) / 256, 256>>>(Wqkv, p_Wqkv);
    hgemm_nt<<<dim3(CDIM / 128, SEQ / 128), 256, HGEMM_SMEM>>>(
        p_hs, p_Wqkv, p_mixed, SEQ, CDIM, HID);
    conv_silu_kernel<<<(SEQ * CDIM) / 256, 256>>>(p_mixed, convw, p_qkv);
    l2norm_kernel<<<(SEQ * NH) / 8, 256>>>(p_qkv);

    cudaStreamWaitEvent(0, g_evAB, 0);
    scan_kernel<<<64, 128>>>(p_qkv, p_eg, p_beta, p_core);

    cudaStreamWaitEvent(0, g_evZ, 0);
    gate_norm_h_kernel<<<(SEQ * NH) / 8, 256>>>(p_core, p_z, norm_w, p_gat);

    cudaStreamWaitEvent(0, g_evWout, 0);
    hgemm_nt<<<dim3(HID / 128, SEQ / 128), 256, HGEMM_SMEM>>>(
        p_gat, p_Wout, out, SEQ, HID, VALD);
}

// round 6
// speedup vs baseline: 4.3281x; 1.3357x over previous
#include <cuda_runtime.h>
#include <cuda_fp16.h>
#include <math.h>
#include <stdint.h>

#define SEQ   2048
#define HID   2048
#define NH    16
#define DK    64
#define DV    128
#define KEYD  1024
#define VALD  2048
#define CDIM  4096   // 2*KEYD + VALD

// ------------------------------------------------------------------
// Scratch (device globals; no allocation allowed)
// ------------------------------------------------------------------
__device__ float g_mixed[SEQ * CDIM];   // pre-conv qkv (fp32)
__device__ float g_qkv  [SEQ * CDIM];   // post conv+silu (q | k | v)
__device__ float g_eg   [SEQ * NH];     // exp(log-decay)
__device__ float g_beta [SEQ * NH];
__device__ float g_z    [SEQ * VALD];
__device__ float g_core [SEQ * VALD];

__device__ __half g_hs_h  [SEQ  * HID];
__device__ __half g_Wqkv_h[CDIM * HID];
__device__ __half g_Wz_h  [VALD * HID];
__device__ __half g_Wout_h[HID  * VALD];
__device__ __half g_gat_h [SEQ  * VALD];

// ------------------------------------------------------------------
// PTX helpers (base ISA only: cp.async / ldmatrix / mma.sync)
// ------------------------------------------------------------------
__device__ __forceinline__ uint32_t smem_u32(const void* p) {
    uint32_t a;
    asm("{ .reg .u64 t; cvta.to.shared.u64 t, %1; cvt.u32.u64 %0, t; }"
        : "=r"(a) : "l"(p));
    return a;
}
__device__ __forceinline__ void cp_async16(uint32_t s, const void* g) {
    asm volatile("cp.async.cg.shared.global [%0], [%1], 16;" :: "r"(s), "l"(g));
}
__device__ __forceinline__ void cp_commit() {
    asm volatile("cp.async.commit_group;");
}
template <int N>
__device__ __forceinline__ void cp_wait() {
    asm volatile("cp.async.wait_group %0;" :: "n"(N));
}
__device__ __forceinline__ void ldsm4(uint32_t& r0, uint32_t& r1,
                                      uint32_t& r2, uint32_t& r3, uint32_t a) {
    asm volatile("ldmatrix.sync.aligned.m8n8.x4.shared.b16 {%0,%1,%2,%3}, [%4];"
                 : "=r"(r0), "=r"(r1), "=r"(r2), "=r"(r3) : "r"(a));
}
__device__ __forceinline__ void mma16816(float* d, const uint32_t* a,
                                         uint32_t b0, uint32_t b1) {
    asm volatile(
        "mma.sync.aligned.m16n8k16.row.col.f32.f16.f16.f32 "
        "{%0,%1,%2,%3}, {%4,%5,%6,%7}, {%8,%9}, {%0,%1,%2,%3};"
        : "+f"(d[0]), "+f"(d[1]), "+f"(d[2]), "+f"(d[3])
        : "r"(a[0]), "r"(a[1]), "r"(a[2]), "r"(a[3]), "r"(b0), "r"(b1));
}
#define SW(off) ((off) ^ (((off) >> 3) & 0x70))

// ------------------------------------------------------------------
// fp16 NT GEMM via mma.sync: C[M,N] = A[M,K] * B[N,K]^T (fp32 out)
// BM=BN=128, BK=64, 256 threads (8 warps, 4x2), double-buffered cp.async.
// ------------------------------------------------------------------
#define HGEMM_SMEM (4 * 16384)

__global__ __launch_bounds__(256)
void hgemm_nt(const __half* __restrict__ A, const __half* __restrict__ B,
              float* __restrict__ C, int M, int N, int K)
{
    extern __shared__ __align__(1024) char sm[];
    const int tid  = threadIdx.x;
    const int wid  = tid >> 5, lane = tid & 31;
    const int tileN = blockIdx.x, tileM = blockIdx.y;
    const int wm = (wid >> 1) * 32;     // warp M offset
    const int wn = (wid & 1) * 64;      // warp N offset

    const uint32_t sbase = smem_u32(sm);

    const char* Ag = (const char*)(A + (size_t)tileM * 128 * K);
    const char* Bg = (const char*)(B + (size_t)tileN * 128 * K);
    const size_t rs = (size_t)K * 2;

    const int crow = tid >> 3;
    const int ccol = (tid & 7) * 16;

    int offA[2], offB[4];
#pragma unroll
    for (int mt = 0; mt < 2; mt++)
        offA[mt] = (wm + mt * 16 + (lane & 15)) * 128 + (lane >> 4) * 16;
#pragma unroll
    for (int j2 = 0; j2 < 4; j2++)
        offB[j2] = (wn + j2 * 16 + (lane & 7) + ((lane >> 4) & 1) * 8) * 128
                 + ((lane >> 3) & 1) * 16;

    float acc[2][8][4];
#pragma unroll
    for (int mt = 0; mt < 2; mt++)
#pragma unroll
        for (int nt = 0; nt < 8; nt++)
#pragma unroll
            for (int r = 0; r < 4; r++) acc[mt][nt][r] = 0.f;

    const int chunks = K >> 6;

#define ISSUE(i, b)                                                          \
    do {                                                                     \
        uint32_t sA = sbase + (b) * 32768;                                   \
        uint32_t sB = sA + 16384;                                            \
        const char* gA = Ag + (size_t)(i) * 128 + ccol;                      \
        const char* gB = Bg + (size_t)(i) * 128 + ccol;                      \
        _Pragma("unroll")                                                    \
        for (int p = 0; p < 4; p++) {                                        \
            int row = crow + p * 32;                                         \
            int so  = SW(row * 128 + ccol);                                  \
            cp_async16(sA + so, gA + row * rs);                              \
            cp_async16(sB + so, gB + row * rs);                              \
        }                                                                    \
        cp_commit();                                                         \
    } while (0)

    ISSUE(0, 0);

    for (int i = 0; i < chunks; i++) {
        const int b = i & 1;
        if (i + 1 < chunks) { ISSUE(i + 1, b ^ 1); cp_wait<1>(); }
        else                { cp_wait<0>(); }
        __syncthreads();

        const uint32_t sA = sbase + b * 32768;
        const uint32_t sB = sA + 16384;
#pragma unroll
        for (int ks = 0; ks < 4; ks++) {
            uint32_t af[2][4];
#pragma unroll
            for (int mt = 0; mt < 2; mt++) {
                int off = offA[mt] + ks * 32;
                ldsm4(af[mt][0], af[mt][1], af[mt][2], af[mt][3], sA + SW(off));
            }
            uint32_t bf[8][2];
#pragma unroll
            for (int j2 = 0; j2 < 4; j2++) {
                int off = offB[j2] + ks * 32;
                uint32_t r0, r1, r2, r3;
                ldsm4(r0, r1, r2, r3, sB + SW(off));
                bf[2 * j2][0] = r0; bf[2 * j2][1] = r1;
                bf[2 * j2 + 1][0] = r2; bf[2 * j2 + 1][1] = r3;
            }
#pragma unroll
            for (int mt = 0; mt < 2; mt++)
#pragma unroll
                for (int nt = 0; nt < 8; nt++)
                    mma16816(acc[mt][nt], af[mt], bf[nt][0], bf[nt][1]);
        }
        __syncthreads();
    }
#undef ISSUE

    const int gid = lane >> 2, ctg = lane & 3;
#pragma unroll
    for (int mt = 0; mt < 2; mt++) {
        int m0 = tileM * 128 + wm + mt * 16 + gid;
#pragma unroll
        for (int nt = 0; nt < 8; nt++) {
            int n0 = tileN * 128 + wn + nt * 8 + ctg * 2;
            *(float2*)(C + (size_t)m0 * N + n0) =
                make_float2(acc[mt][nt][0], acc[mt][nt][1]);
            *(float2*)(C + (size_t)(m0 + 8) * N + n0) =
                make_float2(acc[mt][nt][2], acc[mt][nt][3]);
        }
    }
}

// ------------------------------------------------------------------
// fp32 -> fp16 conversion, 8 elems/thread.
// ------------------------------------------------------------------
__global__ __launch_bounds__(256)
void f2h_kernel(const float* __restrict__ in, __half* __restrict__ out)
{
    int idx = (blockIdx.x * 256 + threadIdx.x) * 8;
    float4 x0 = *(const float4*)(in + idx);
    float4 x1 = *(const float4*)(in + idx + 4);
    union { __half2 h[4]; uint4 u; } r;
    r.h[0] = __floats2half2_rn(x0.x, x0.y);
    r.h[1] = __floats2half2_rn(x0.z, x0.w);
    r.h[2] = __floats2half2_rn(x1.x, x1.y);
    r.h[3] = __floats2half2_rn(x1.z, x1.w);
    *(uint4*)(out + idx) = r.u;
}

// ------------------------------------------------------------------
// Depthwise causal conv (K=4) along time + SiLU.
// ------------------------------------------------------------------
__global__ __launch_bounds__(256)
void conv_silu_kernel(const float* __restrict__ mixed,
                      const float* __restrict__ w,
                      float* __restrict__ out)
{
    int idx = blockIdx.x * blockDim.x + threadIdx.x;   // t*CDIM + c
    int t = idx >> 12;
    int c = idx & (CDIM - 1);
    float w0 = w[c * 4 + 0], w1 = w[c * 4 + 1], w2 = w[c * 4 + 2], w3 = w[c * 4 + 3];
    float acc = w3 * mixed[idx];
    if (t >= 1) acc = fmaf(w2, mixed[idx - CDIM],     acc);
    if (t >= 2) acc = fmaf(w1, mixed[idx - 2 * CDIM], acc);
    if (t >= 3) acc = fmaf(w0, mixed[idx - 3 * CDIM], acc);
    out[idx] = acc / (1.f + expf(-acc));   // silu
}

// ------------------------------------------------------------------
// a/b projections -> eg = exp(log-decay) and beta. One warp per (t,h).
// ------------------------------------------------------------------
__global__ __launch_bounds__(256)
void ab_kernel(const float* __restrict__ hs,
               const float* __restrict__ Wa,
               const float* __restrict__ Wb,
               const float* __restrict__ A_log,
               const float* __restrict__ dt_bias,
               float* __restrict__ eg,
               float* __restrict__ beta)
{
    int w    = blockIdx.x * (blockDim.x >> 5) + (threadIdx.x >> 5);
    int lane = threadIdx.x & 31;
    if (w >= SEQ * NH) return;
    int t = w >> 4, h = w & 15;

    const float4* x4 = (const float4*)(hs + (size_t)t * HID);
    const float4* a4 = (const float4*)(Wa + (size_t)h * HID);
    const float4* b4 = (const float4*)(Wb + (size_t)h * HID);

    float sa = 0.f, sb = 0.f;
    for (int i = lane; i < HID / 4; i += 32) {
        float4 x = x4[i], a = a4[i], b = b4[i];
        sa += x.x * a.x + x.y * a.y + x.z * a.z + x.w * a.w;
        sb += x.x * b.x + x.y * b.y + x.z * b.z + x.w * b.w;
    }
#pragma unroll
    for (int o = 16; o; o >>= 1) {
        sa += __shfl_xor_sync(0xffffffffu, sa, o);
        sb += __shfl_xor_sync(0xffffffffu, sb, o);
    }
    if (lane == 0) {
        float av = sa + dt_bias[h];
        float sp = (av > 20.f) ? av : log1pf(expf(av));   // softplus
        eg[t * NH + h]   = expf(-expf(A_log[h]) * sp);
        beta[t * NH + h] = 1.f / (1.f + expf(-sb));
    }
}

// ------------------------------------------------------------------
// L2-normalize q (scale 1/sqrt(DK)) and k, per (t,h). Warp per row.
// ------------------------------------------------------------------
__global__ __launch_bounds__(256)
void l2norm_kernel(float* __restrict__ qkv)
{
    int w    = blockIdx.x * (blockDim.x >> 5) + (threadIdx.x >> 5);
    int lane = threadIdx.x & 31;
    if (w >= SEQ * NH) return;
    int t = w >> 4, h = w & 15;

    float2* qp = (float2*)(qkv + (size_t)t * CDIM + h * DK);
    float2* kp = (float2*)(qkv + (size_t)t * CDIM + KEYD + h * DK);
    float2 qv = qp[lane];
    float2 kv = kp[lane];
    float sq = qv.x * qv.x + qv.y * qv.y;
    float sk = kv.x * kv.x + kv.y * kv.y;
#pragma unroll
    for (int o = 16; o; o >>= 1) {
        sq += __shfl_xor_sync(0xffffffffu, sq, o);
        sk += __shfl_xor_sync(0xffffffffu, sk, o);
    }
    float rq = rsqrtf(sq + 1e-6f) * 0.125f;   // * 1/sqrt(64)
    float rk = rsqrtf(sk + 1e-6f);
    qp[lane] = make_float2(qv.x * rq, qv.y * rq);
    kp[lane] = make_float2(kv.x * rk, kv.y * rk);
}

// ------------------------------------------------------------------
// Delta-rule scan: warp-autonomous, no smem/sync, depth-2 prefetch.
// 256 single-warp blocks: warp = (head h = bid>>4, vgroup = bid&15).
// lane: qtr = lane&3 (16 of DK), vl = lane>>2 (8 v's per warp).
// 3 rotating register buffers; loads for t+2 issued while computing t.
// qkv row layout: [ q (KEYD) | k (KEYD) | v (VALD) ]
// ------------------------------------------------------------------
__global__ __launch_bounds__(32)
void scan_kernel(const float* __restrict__ qkv,
                 const float* __restrict__ eg_arr,
                 const float* __restrict__ beta_arr,
                 float* __restrict__ core)
{
    const int w    = blockIdx.x;
    const int h    = w >> 4;
    const int vg   = w & 15;
    const int lane = threadIdx.x;
    const int qtr  = lane & 3;
    const int vl   = lane >> 2;
    const int v    = vg * 8 + vl;

    const float* kp = qkv + KEYD + h * DK + qtr * 16;
    const float* qp = qkv + h * DK + qtr * 16;
    const float* vp = qkv + 2 * KEYD + h * DV + v;

    float4 kb[3][4], qb[3][4];
    float  vb[3], eb[3], bb[3];
    float  S[16];
#pragma unroll
    for (int i = 0; i < 16; i++) S[i] = 0.f;

#define LOADT(i, tt)                                                   \
    do {                                                               \
        int _t = (tt); if (_t >= SEQ) _t = SEQ - 1;                    \
        size_t _o = (size_t)_t * CDIM;                                 \
        const float4* _k4 = (const float4*)(kp + _o);                  \
        const float4* _q4 = (const float4*)(qp + _o);                  \
        kb[i][0] = _k4[0]; kb[i][1] = _k4[1];                          \
        kb[i][2] = _k4[2]; kb[i][3] = _k4[3];                          \
        qb[i][0] = _q4[0]; qb[i][1] = _q4[1];                          \
        qb[i][2] = _q4[2]; qb[i][3] = _q4[3];                          \
        vb[i] = vp[_o];                                                \
        eb[i] = eg_arr[_t * NH + h];                                   \
        bb[i] = beta_arr[_t * NH + h];                                 \
    } while (0)

#define COMPUTE(i, t)                                                      \
    do {                                                                   \
        float r0 = 0.f, r1 = 0.f, r2 = 0.f, r3 = 0.f;                      \
        _Pragma("unroll")                                                  \
        for (int j = 0; j < 4; j++) {                                      \
            r0 = fmaf(kb[i][j].x, S[4 * j + 0], r0);                       \
            r1 = fmaf(kb[i][j].y, S[4 * j + 1], r1);                       \
            r2 = fmaf(kb[i][j].z, S[4 * j + 2], r2);                       \
            r3 = fmaf(kb[i][j].w, S[4 * j + 3], r3);                       \
        }                                                                  \
        float raw = (r0 + r1) + (r2 + r3);                                 \
        raw += __shfl_xor_sync(0xffffffffu, raw, 1);                       \
        raw += __shfl_xor_sync(0xffffffffu, raw, 2);                       \
        float _eg = eb[i];                                                 \
        float dl = (vb[i] - _eg * raw) * bb[i];                            \
        float o0 = 0.f, o1 = 0.f, o2 = 0.f, o3 = 0.f;                      \
        _Pragma("unroll")                                                  \
        for (int j = 0; j < 4; j++) {                                      \
            float s0 = fmaf(S[4 * j + 0], _eg, kb[i][j].x * dl);           \
            float s1 = fmaf(S[4 * j + 1], _eg, kb[i][j].y * dl);           \
            float s2 = fmaf(S[4 * j + 2], _eg, kb[i][j].z * dl);           \
            float s3 = fmaf(S[4 * j + 3], _eg, kb[i][j].w * dl);           \
            S[4 * j + 0] = s0; S[4 * j + 1] = s1;                          \
            S[4 * j + 2] = s2; S[4 * j + 3] = s3;                          \
            o0 = fmaf(qb[i][j].x, s0, o0);                                 \
            o1 = fmaf(qb[i][j].y, s1, o1);                                 \
            o2 = fmaf(qb[i][j].z, s2, o2);                                 \
            o3 = fmaf(qb[i][j].w, s3, o3);                                 \
        }                                                                  \
        float o = (o0 + o1) + (o2 + o3);                                   \
        o += __shfl_xor_sync(0xffffffffu, o, 1);                           \
        o += __shfl_xor_sync(0xffffffffu, o, 2);                           \
        if (qtr == 0 && (t) < SEQ)                                         \
            core[(size_t)(t) * VALD + h * DV + v] = o;                     \
    } while (0)

    LOADT(0, 0);
    LOADT(1, 1);

    for (int t = 0; t < SEQ; t += 3) {
        LOADT(2, t + 2);  COMPUTE(0, t);
        LOADT(0, t + 3);  COMPUTE(1, t + 1);
        LOADT(1, t + 4);  COMPUTE(2, t + 2);
    }
#undef LOADT
#undef COMPUTE
}

// ------------------------------------------------------------------
// Gated RMSNorm + SiLU(z) gate, fp16 output. Warp per (t,h).
// ------------------------------------------------------------------
__global__ __launch_bounds__(256)
void gate_norm_h_kernel(const float* __restrict__ core,
                        const float* __restrict__ z,
                        const float* __restrict__ norm_w,
                        __half* __restrict__ out)
{
    int w    = blockIdx.x * (blockDim.x >> 5) + (threadIdx.x >> 5);
    int lane = threadIdx.x & 31;
    if (w >= SEQ * NH) return;
    int t = w >> 4, h = w & 15;
    size_t base = (size_t)t * VALD + h * DV;

    float4 cv = ((const float4*)(core + base))[lane];
    float ss = cv.x * cv.x + cv.y * cv.y + cv.z * cv.z + cv.w * cv.w;
#pragma unroll
    for (int o = 16; o; o >>= 1) ss += __shfl_xor_sync(0xffffffffu, ss, o);
    float r = rsqrtf(ss * (1.f / DV) + 1e-6f);

    float4 zv = ((const float4*)(z + base))[lane];
    float4 nw = ((const float4*)norm_w)[lane];
    float v0 = cv.x * r * nw.x * (zv.x / (1.f + expf(-zv.x)));
    float v1 = cv.y * r * nw.y * (zv.y / (1.f + expf(-zv.y)));
    float v2 = cv.z * r * nw.z * (zv.z / (1.f + expf(-zv.z)));
    float v3 = cv.w * r * nw.w * (zv.w / (1.f + expf(-zv.w)));

    union { __half2 h[2]; uint2 u; } o2;
    o2.h[0] = __floats2half2_rn(v0, v1);
    o2.h[1] = __floats2half2_rn(v2, v3);
    *(uint2*)(out + base + lane * 4) = o2.u;
}

// ------------------------------------------------------------------
// Launch
// ------------------------------------------------------------------
static cudaStream_t g_sB = nullptr;
static cudaEvent_t  g_evFork = nullptr, g_evHs = nullptr, g_evAB = nullptr,
                    g_evZ = nullptr, g_evWout = nullptr;

extern "C" void kernel_launch(void* const* d_in, const int* in_sizes, int n_in,
                              void* d_out, int out_size)
{
    const float* hs      = (const float*)d_in[0];
    const float* Wqkv    = (const float*)d_in[1];
    const float* Wa      = (const float*)d_in[2];
    const float* Wb      = (const float*)d_in[3];
    const float* Wz      = (const float*)d_in[4];
    const float* convw   = (const float*)d_in[5];
    const float* A_log   = (const float*)d_in[6];
    const float* dt_bias = (const float*)d_in[7];
    const float* norm_w  = (const float*)d_in[8];
    const float* Wout    = (const float*)d_in[9];
    float* out = (float*)d_out;

    if (!g_sB) {
        cudaStreamCreateWithFlags(&g_sB, cudaStreamNonBlocking);
        cudaEventCreateWithFlags(&g_evFork, cudaEventDisableTiming);
        cudaEventCreateWithFlags(&g_evHs,   cudaEventDisableTiming);
        cudaEventCreateWithFlags(&g_evAB,   cudaEventDisableTiming);
        cudaEventCreateWithFlags(&g_evZ,    cudaEventDisableTiming);
        cudaEventCreateWithFlags(&g_evWout, cudaEventDisableTiming);
        cudaFuncSetAttribute(hgemm_nt,
                             cudaFuncAttributeMaxDynamicSharedMemorySize, HGEMM_SMEM);
    }

    float *p_mixed, *p_qkv, *p_eg, *p_beta, *p_z, *p_core;
    __half *p_hs, *p_Wqkv, *p_Wz, *p_Wout, *p_gat;
    cudaGetSymbolAddress((void**)&p_mixed, g_mixed);
    cudaGetSymbolAddress((void**)&p_qkv,   g_qkv);
    cudaGetSymbolAddress((void**)&p_eg,    g_eg);
    cudaGetSymbolAddress((void**)&p_beta,  g_beta);
    cudaGetSymbolAddress((void**)&p_z,     g_z);
    cudaGetSymbolAddress((void**)&p_core,  g_core);
    cudaGetSymbolAddress((void**)&p_hs,    g_hs_h);
    cudaGetSymbolAddress((void**)&p_Wqkv,  g_Wqkv_h);
    cudaGetSymbolAddress((void**)&p_Wz,    g_Wz_h);
    cudaGetSymbolAddress((void**)&p_Wout,  g_Wout_h);
    cudaGetSymbolAddress((void**)&p_gat,   g_gat_h);

    // Fork side stream
    cudaEventRecord(g_evFork, 0);
    cudaStreamWaitEvent(g_sB, g_evFork, 0);

    // Main: hs -> fp16 (A operand for qkv and z GEMMs)
    f2h_kernel<<<(SEQ * HID / 8) / 256, 256>>>(hs, p_hs);
    cudaEventRecord(g_evHs, 0);

    // Side: eg/beta; Wz->fp16; z GEMM; Wout->fp16
    ab_kernel<<<(SEQ * NH) / 8, 256, 0, g_sB>>>(hs, Wa, Wb, A_log, dt_bias, p_eg, p_beta);
    cudaEventRecord(g_evAB, g_sB);
    f2h_kernel<<<(VALD * HID / 8) / 256, 256, 0, g_sB>>>(Wz, p_Wz);
    cudaStreamWaitEvent(g_sB, g_evHs, 0);
    hgemm_nt<<<dim3(VALD / 128, SEQ / 128), 256, HGEMM_SMEM, g_sB>>>(
        p_hs, p_Wz, p_z, SEQ, VALD, HID);
    cudaEventRecord(g_evZ, g_sB);
    f2h_kernel<<<(HID * VALD / 8) / 256, 256, 0, g_sB>>>(Wout, p_Wout);
    cudaEventRecord(g_evWout, g_sB);

    // Main: qkv GEMM chain
    f2h_kernel<<<(CDIM * HID / 8) / 256, 256>>>(Wqkv, p_Wqkv);
    hgemm_nt<<<dim3(CDIM / 128, SEQ / 128), 256, HGEMM_SMEM>>>(
        p_hs, p_Wqkv, p_mixed, SEQ, CDIM, HID);
    conv_silu_kernel<<<(SEQ * CDIM) / 256, 256>>>(p_mixed, convw, p_qkv);
    l2norm_kernel<<<(SEQ * NH) / 8, 256>>>(p_qkv);

    cudaStreamWaitEvent(0, g_evAB, 0);
    scan_kernel<<<256, 32>>>(p_qkv, p_eg, p_beta, p_core);

    cudaStreamWaitEvent(0, g_evZ, 0);
    gate_norm_h_kernel<<<(SEQ * NH) / 8, 256>>>(p_core, p_z, norm_w, p_gat);

    cudaStreamWaitEvent(0, g_evWout, 0);
    hgemm_nt<<<dim3(HID / 128, SEQ / 128), 256, HGEMM_SMEM>>>(
        p_gat, p_Wout, out, SEQ, HID, VALD);
}